// round 13
// baseline (speedup 1.0000x reference)
#include <cuda_runtime.h>
#include <cuda_bf16.h>
#include <cstdint>

// Plane2Depth: out[b,0,H,W] = 1 / max( s*(p*u + q*v + r), 0.1 )
// [p,q,r,s] = Wmat @ feat[b,:,H/4,W/4];  norm cancels algebraically.
//
// R12 = R7 (best: 9.47us ncu, occ 79%) with a non-blocking exit:
//  - warps 1..5: compute, STS, bar.arrive (named barrier 1) -> retire NOW.
//  - warp 0:     compute, STS, bar.sync; thread 0 then issues the 12KB
//                cp.async.bulk and drains it. SMEM is freed only at full-CTA
//                exit (thread 0), so the in-flight bulk read stays safe.
// 5/6 of each CTA's warp slots recycle to the next CTA during the TMA drain
// instead of idling behind __syncthreads + wait_group 0.

#define IN_H   192
#define IN_W   192
#define BATCH  16
#define OUT_HW 768          // 192*4
#define PLANE  (IN_H * IN_W)
#define TILE_BYTES (4 * OUT_HW * 4)   // 12288

__global__ __launch_bounds__(IN_W)
void plane2depth_kernel(const float* __restrict__ feat,
                        const float4* __restrict__ Wmat,
                        float* __restrict__ out)
{
    __shared__ __align__(16) float sm[4][OUT_HW];   // 12288 B

    const int w = threadIdx.x;      // input column (0..191)
    const int h = blockIdx.x;       // input row
    const int b = blockIdx.y;       // batch

    // ---- load 4 channels of this pixel (each warp-coalesced 128B) ----
    const float* fp = feat + (size_t)b * 4 * PLANE + (size_t)h * IN_W + w;
    float f0 = fp[0];
    float f1 = fp[PLANE];
    float f2 = fp[2 * PLANE];
    float f3 = fp[3 * PLANE];

    // ---- W matrix: 4 vector loads, uniform broadcast, L1-resident ----
    float4 m0 = __ldg(Wmat + 0);
    float4 m1 = __ldg(Wmat + 1);
    float4 m2 = __ldg(Wmat + 2);
    float4 m3 = __ldg(Wmat + 3);

    float p = fmaf(m0.x, f0, fmaf(m0.y, f1, fmaf(m0.z, f2, m0.w * f3)));
    float q = fmaf(m1.x, f0, fmaf(m1.y, f1, fmaf(m1.z, f2, m1.w * f3)));
    float r = fmaf(m2.x, f0, fmaf(m2.y, f1, fmaf(m2.z, f2, m2.w * f3)));
    float s = fmaf(m3.x, f0, fmaf(m3.y, f1, fmaf(m3.z, f2, m3.w * f3)));

    // fold s:  d = sp*u + sq*v + sr
    float sp = s * p, sq = s * q, sr = s * r;

    const float DMIN = 0.1f;   // 1.0 / MAX_DEPTH
    float pu0 = sp * -0.375f, pu1 = sp * -0.125f,
          pu2 = sp *  0.125f, pu3 = sp *  0.375f;

    float* smr = &sm[0][4 * w];
#pragma unroll
    for (int j = 0; j < 4; j++) {            // output sub-row (v index)
        float vj   = (float)j * 0.25f - 0.375f;
        float base = fmaf(sq, vj, sr);
        float4 o;
        float d;
        d = pu0 + base; d = fmaxf(d, DMIN); o.x = __fdividef(1.0f, d);
        d = pu1 + base; d = fmaxf(d, DMIN); o.y = __fdividef(1.0f, d);
        d = pu2 + base; d = fmaxf(d, DMIN); o.z = __fdividef(1.0f, d);
        d = pu3 + base; d = fmaxf(d, DMIN); o.w = __fdividef(1.0f, d);
        *(float4*)(smr + (size_t)j * OUT_HW) = o;   // STS.128, conflict-free
    }

    // Producer/consumer barrier: warps 1..5 arrive (non-blocking) and RETIRE;
    // warp 0 syncs, then thread 0 ships the tile.
    if (threadIdx.x >= 32) {
        asm volatile("bar.arrive 1, %0;" :: "r"(IN_W) : "memory");
        return;
    }
    asm volatile("bar.sync 1, %0;" :: "r"(IN_W) : "memory");

    if (threadIdx.x == 0) {
        float* dst = out + ((size_t)b * OUT_HW + (size_t)(4 * h)) * OUT_HW;
        uint32_t saddr;
        asm volatile("{ .reg .u64 t; cvta.to.shared.u64 t, %1; cvt.u32.u64 %0, t; }"
                     : "=r"(saddr) : "l"(&sm[0][0]));
        asm volatile("fence.proxy.async.shared::cta;" ::: "memory");
        asm volatile("cp.async.bulk.global.shared::cta.bulk_group [%0], [%1], %2;"
                     :: "l"(dst), "r"(saddr), "r"((int)TILE_BYTES) : "memory");
        asm volatile("cp.async.bulk.commit_group;" ::: "memory");
        asm volatile("cp.async.bulk.wait_group 0;" ::: "memory");
    }
}

extern "C" void kernel_launch(void* const* d_in, const int* in_sizes, int n_in,
                              void* d_out, int out_size)
{
    const float*  feat = (const float*)d_in[0];    // (16,4,192,192) f32
    const float4* Wmat = (const float4*)d_in[1];   // (4,4) f32
    float* out = (float*)d_out;                    // (16,1,768,768) f32

    dim3 grid(IN_H, BATCH);      // 192 x 16 = 3072 blocks
    dim3 block(IN_W);            // 192 threads = one input row
    plane2depth_kernel<<<grid, block>>>(feat, Wmat, out);
}

// round 14
// speedup vs baseline: 1.3851x; 1.3851x over previous
#include <cuda_runtime.h>
#include <cuda_bf16.h>
#include <cstdint>

// Plane2Depth: out[b,0,H,W] = 1 / max( s*(p*u + q*v + r), 0.1 )
// [p,q,r,s] = Wmat @ feat[b,:,H/4,W/4];  norm cancels algebraically.
//
// R13 = R7 skeleton (best: 9.47us ncu) with 2 pixels per thread:
//  - block = 96 threads (3 warps); thread w owns pixels (h, 2w) and (h, 2w+1)
//  - channel loads are float2 (LDG.64, same coalescing, half the LDG count)
//  - W-load / addressing / barrier overhead amortized over 2x work;
//    two independent matvec->MUFU chains per thread (2x ILP)
//  - smem 12KB/CTA -> ~18 CTAs/SM -> ~54 warps/SM occupancy
//  - exit: one 12KB cp.async.bulk, thread 0 drains, NO trailing sync
//    (R10-verified: SMEM freed only at full-CTA exit, pinned by thread 0)

#define IN_H   192
#define IN_W   192
#define BATCH  16
#define OUT_HW 768          // 192*4
#define PLANE  (IN_H * IN_W)
#define TILE_BYTES (4 * OUT_HW * 4)   // 12288

__global__ __launch_bounds__(IN_W / 2)
void plane2depth_kernel(const float* __restrict__ feat,
                        const float4* __restrict__ Wmat,
                        float* __restrict__ out)
{
    __shared__ __align__(16) float sm[4][OUT_HW];   // 12288 B

    const int w = threadIdx.x;      // pixel pair index (0..95)
    const int h = blockIdx.x;       // input row
    const int b = blockIdx.y;       // batch

    // ---- load 4 channels for BOTH pixels (LDG.64, warp-coalesced) ----
    const float2* fp = (const float2*)(feat + (size_t)b * 4 * PLANE
                                            + (size_t)h * IN_W) + w;
    float2 c0 = fp[0];
    float2 c1 = fp[PLANE / 2];          // +1 channel (PLANE floats)
    float2 c2 = fp[PLANE];              // +2 channels
    float2 c3 = fp[3 * (PLANE / 2)];    // +3 channels

    // ---- W matrix: 4 vector loads, uniform broadcast, L1-resident ----
    float4 m0 = __ldg(Wmat + 0);
    float4 m1 = __ldg(Wmat + 1);
    float4 m2 = __ldg(Wmat + 2);
    float4 m3 = __ldg(Wmat + 3);

    // ---- two independent matvecs (pixel A = .x, pixel B = .y) ----
    float pA = fmaf(m0.x, c0.x, fmaf(m0.y, c1.x, fmaf(m0.z, c2.x, m0.w * c3.x)));
    float pB = fmaf(m0.x, c0.y, fmaf(m0.y, c1.y, fmaf(m0.z, c2.y, m0.w * c3.y)));
    float qA = fmaf(m1.x, c0.x, fmaf(m1.y, c1.x, fmaf(m1.z, c2.x, m1.w * c3.x)));
    float qB = fmaf(m1.x, c0.y, fmaf(m1.y, c1.y, fmaf(m1.z, c2.y, m1.w * c3.y)));
    float rA = fmaf(m2.x, c0.x, fmaf(m2.y, c1.x, fmaf(m2.z, c2.x, m2.w * c3.x)));
    float rB = fmaf(m2.x, c0.y, fmaf(m2.y, c1.y, fmaf(m2.z, c2.y, m2.w * c3.y)));
    float sA = fmaf(m3.x, c0.x, fmaf(m3.y, c1.x, fmaf(m3.z, c2.x, m3.w * c3.x)));
    float sB = fmaf(m3.x, c0.y, fmaf(m3.y, c1.y, fmaf(m3.z, c2.y, m3.w * c3.y)));

    float spA = sA * pA, sqA = sA * qA, srA = sA * rA;
    float spB = sB * pB, sqB = sB * qB, srB = sB * rB;

    const float DMIN = 0.1f;   // 1.0 / MAX_DEPTH
    float puA0 = spA * -0.375f, puA1 = spA * -0.125f,
          puA2 = spA *  0.125f, puA3 = spA *  0.375f;
    float puB0 = spB * -0.375f, puB1 = spB * -0.125f,
          puB2 = spB *  0.125f, puB3 = spB *  0.375f;

    float* smr = &sm[0][8 * w];
#pragma unroll
    for (int j = 0; j < 4; j++) {            // output sub-row (v index)
        float vj    = (float)j * 0.25f - 0.375f;
        float baseA = fmaf(sqA, vj, srA);
        float baseB = fmaf(sqB, vj, srB);
        float4 oA, oB;
        float d;
        d = puA0 + baseA; d = fmaxf(d, DMIN); oA.x = __fdividef(1.0f, d);
        d = puB0 + baseB; d = fmaxf(d, DMIN); oB.x = __fdividef(1.0f, d);
        d = puA1 + baseA; d = fmaxf(d, DMIN); oA.y = __fdividef(1.0f, d);
        d = puB1 + baseB; d = fmaxf(d, DMIN); oB.y = __fdividef(1.0f, d);
        d = puA2 + baseA; d = fmaxf(d, DMIN); oA.z = __fdividef(1.0f, d);
        d = puB2 + baseB; d = fmaxf(d, DMIN); oB.z = __fdividef(1.0f, d);
        d = puA3 + baseA; d = fmaxf(d, DMIN); oA.w = __fdividef(1.0f, d);
        d = puB3 + baseB; d = fmaxf(d, DMIN); oB.w = __fdividef(1.0f, d);
        *(float4*)(smr + (size_t)j * OUT_HW)     = oA;   // STS.128
        *(float4*)(smr + (size_t)j * OUT_HW + 4) = oB;   // STS.128
    }

    __syncthreads();   // 3 warps; all STS complete before the bulk read

    // One 12KB bulk copy; only thread 0 waits. No trailing sync — SMEM
    // stays allocated until the whole CTA exits (thread 0 pins it).
    if (threadIdx.x == 0) {
        float* dst = out + ((size_t)b * OUT_HW + (size_t)(4 * h)) * OUT_HW;
        uint32_t saddr;
        asm volatile("{ .reg .u64 t; cvta.to.shared.u64 t, %1; cvt.u32.u64 %0, t; }"
                     : "=r"(saddr) : "l"(&sm[0][0]));
        asm volatile("fence.proxy.async.shared::cta;" ::: "memory");
        asm volatile("cp.async.bulk.global.shared::cta.bulk_group [%0], [%1], %2;"
                     :: "l"(dst), "r"(saddr), "r"((int)TILE_BYTES) : "memory");
        asm volatile("cp.async.bulk.commit_group;" ::: "memory");
        asm volatile("cp.async.bulk.wait_group 0;" ::: "memory");
    }
}

extern "C" void kernel_launch(void* const* d_in, const int* in_sizes, int n_in,
                              void* d_out, int out_size)
{
    const float*  feat = (const float*)d_in[0];    // (16,4,192,192) f32
    const float4* Wmat = (const float4*)d_in[1];   // (4,4) f32
    float* out = (float*)d_out;                    // (16,1,768,768) f32

    dim3 grid(IN_H, BATCH);      // 192 x 16 = 3072 blocks
    dim3 block(IN_W / 2);        // 96 threads = one input row, 2 px/thread
    plane2depth_kernel<<<grid, block>>>(feat, Wmat, out);
}